// round 2
// baseline (speedup 1.0000x reference)
#include <cuda_runtime.h>

// Problem constants
#define NT    48
#define NE    48
#define BATCH 32
#define VS    512
#define M_ROWS (NT * BATCH)   // 1536 rows for both GEMMs

// Scratch for the two GEMM outputs (3 MB each) — device globals (no alloc)
__device__ float g_A[M_ROWS * VS];   // ta + b1, layout [t*32+b][h]
__device__ float g_E[M_ROWS * VS];   // eb,       layout [n*32+b][h]

// ---------------------------------------------------------------------------
// Stage 1: C[m,h] = sum_v X[m,v] * W1[h, off+v]   (+ b1[h] for z==0)
// Packed-f32x2 GEMM: operands paired along K so fma.rn.f32x2 needs no packing
// MOVs. BM=BN=64, BK=16, 128 threads, 8x4 micro-tile (cols strided by 16).
// ---------------------------------------------------------------------------
#define BM 64
#define BN 64
#define BK 16

__global__ __launch_bounds__(128) void gemm_kernel(
    const float* __restrict__ Tg, const float* __restrict__ Eg,
    const float* __restrict__ W1, const float* __restrict__ b1)
{
    const int z = blockIdx.z;
    const float* __restrict__ X = z ? Eg : Tg;
    float* __restrict__ C = z ? g_E : g_A;
    const int w_off = z ? VS : 0;

    __shared__ float Xs[BM * BK];        // [m][k], k contiguous (stride 16)
    __shared__ float Ws[4 * BN * 4];     // [kc][col^swz][4k] as float4 units

    const int tid = threadIdx.x;
    const int tx = tid & 15;             // col base: cols tx + 16*j
    const int ty = tid >> 4;             // row group: rows ty*8 + i
    const int m0 = blockIdx.y * BM;
    const int h0 = blockIdx.x * BN;

    unsigned long long acc[8][4];
#pragma unroll
    for (int i = 0; i < 8; i++)
#pragma unroll
        for (int j = 0; j < 4; j++) acc[i][j] = 0ULL;

    // global->shared: float4 id f = tid and tid+128 over 256 float4s
    const int r1 = tid >> 2;             // 0..31 (and +32)
    const int c1 = tid & 3;              // k-chunk 0..3

    const float* xg = X  + (size_t)(m0 + r1) * VS + c1 * 4;
    const float* wg = W1 + (size_t)(h0 + r1) * (2 * VS) + w_off + c1 * 4;

    for (int k0 = 0; k0 < VS; k0 += BK) {
        float4 x0 = *(const float4*)(xg + k0);
        float4 x1 = *(const float4*)(xg + 32 * VS + k0);
        float4 w0 = *(const float4*)(wg + k0);
        float4 w1 = *(const float4*)(wg + 32 * (2 * VS) + k0);

        __syncthreads();   // previous iteration's compute done before overwrite
        *(float4*)&Xs[r1 * BK + c1 * 4]        = x0;
        *(float4*)&Xs[(r1 + 32) * BK + c1 * 4] = x1;
        ((float4*)Ws)[c1 * 64 + (r1        ^ (c1 * 2))] = w0;
        ((float4*)Ws)[c1 * 64 + ((r1 + 32) ^ (c1 * 2))] = w1;
        __syncthreads();

#pragma unroll
        for (int kc = 0; kc < 4; kc++) {
            ulonglong2 b[4];
#pragma unroll
            for (int j = 0; j < 4; j++)
                b[j] = ((const ulonglong2*)Ws)[kc * 64 + ((tx + 16 * j) ^ (kc * 2))];
#pragma unroll
            for (int i = 0; i < 8; i++) {
                ulonglong2 a = *(const ulonglong2*)&Xs[(ty * 8 + i) * BK + kc * 4];
#pragma unroll
                for (int j = 0; j < 4; j++) {
                    asm("fma.rn.f32x2 %0, %1, %2, %0;"
                        : "+l"(acc[i][j]) : "l"(a.x), "l"(b[j].x));
                    asm("fma.rn.f32x2 %0, %1, %2, %0;"
                        : "+l"(acc[i][j]) : "l"(a.y), "l"(b[j].y));
                }
            }
        }
    }

    // epilogue: unpack even/odd-k partial sums, add, bias, scalar stores
#pragma unroll
    for (int j = 0; j < 4; j++) {
        const int h = h0 + tx + 16 * j;
        const float bias = (z == 0) ? __ldg(b1 + h) : 0.f;
#pragma unroll
        for (int i = 0; i < 8; i++) {
            float lo, hi;
            asm("mov.b64 {%0,%1}, %2;" : "=f"(lo), "=f"(hi) : "l"(acc[i][j]));
            C[(size_t)(m0 + ty * 8 + i) * VS + h] = lo + hi + bias;
        }
    }
}

// ---------------------------------------------------------------------------
// Stage 2: out[t,n,b] = sum_h w2[h]*tanh(A[t,b,h] + E[n,b,h]) + b2
// Block = (b, t-tile of 12). All 48 E rows for this b staged in SMEM once.
// w2 and the A row live in registers. Warp w covers n = w, w+8, ...
// ---------------------------------------------------------------------------
#define TT 12

__device__ __forceinline__ float tanh_fast(float x) {
    float y;
    asm("tanh.approx.f32 %0, %1;" : "=f"(y) : "f"(x));
    return y;
}

__global__ __launch_bounds__(256) void fuse_kernel(
    const float* __restrict__ W2, const float* __restrict__ b2,
    float* __restrict__ out)
{
    extern __shared__ float sE[];        // [NE][VS] = 98304 bytes

    const int bb = blockIdx.y;           // batch index
    const int t0 = blockIdx.x * TT;
    const int tid = threadIdx.x;
    const int warp = tid >> 5;
    const int lane = tid & 31;

    // Stage all 48 E rows for this b into SMEM (coalesced float4)
    for (int f = tid; f < NE * (VS / 4); f += 256) {
        const int row = f >> 7;          // 0..47
        const int c   = f & 127;         // float4 within row
        ((float4*)sE)[f] =
            *(const float4*)(g_E + ((size_t)(row * BATCH + bb)) * VS + c * 4);
    }

    // w2 in registers: lane owns h-float4s {lane, lane+32, lane+64, lane+96}
    const float4* W4 = (const float4*)W2;
    float4 w0 = W4[lane], w1 = W4[lane + 32], w2 = W4[lane + 64], w3 = W4[lane + 96];
    const float b2v = __ldg(b2);
    __syncthreads();

    for (int t = t0; t < t0 + TT; t++) {
        const float4* A4 = (const float4*)(g_A + ((size_t)(t * BATCH + bb)) * VS);
        float4 a0 = A4[lane], a1 = A4[lane + 32], a2 = A4[lane + 64], a3 = A4[lane + 96];

        for (int n = warp; n < NE; n += 8) {
            const float4* E4 = (const float4*)(sE + n * VS);
            float4 e0 = E4[lane], e1 = E4[lane + 32], e2 = E4[lane + 64], e3 = E4[lane + 96];

            float s0 = 0.f, s1 = 0.f, s2 = 0.f, s3 = 0.f;
            s0 = fmaf(w0.x, tanh_fast(a0.x + e0.x), s0);
            s1 = fmaf(w0.y, tanh_fast(a0.y + e0.y), s1);
            s2 = fmaf(w0.z, tanh_fast(a0.z + e0.z), s2);
            s3 = fmaf(w0.w, tanh_fast(a0.w + e0.w), s3);
            s0 = fmaf(w1.x, tanh_fast(a1.x + e1.x), s0);
            s1 = fmaf(w1.y, tanh_fast(a1.y + e1.y), s1);
            s2 = fmaf(w1.z, tanh_fast(a1.z + e1.z), s2);
            s3 = fmaf(w1.w, tanh_fast(a1.w + e1.w), s3);
            s0 = fmaf(w2.x, tanh_fast(a2.x + e2.x), s0);
            s1 = fmaf(w2.y, tanh_fast(a2.y + e2.y), s1);
            s2 = fmaf(w2.z, tanh_fast(a2.z + e2.z), s2);
            s3 = fmaf(w2.w, tanh_fast(a2.w + e2.w), s3);
            s0 = fmaf(w3.x, tanh_fast(a3.x + e3.x), s0);
            s1 = fmaf(w3.y, tanh_fast(a3.y + e3.y), s1);
            s2 = fmaf(w3.z, tanh_fast(a3.z + e3.z), s2);
            s3 = fmaf(w3.w, tanh_fast(a3.w + e3.w), s3);

            float acc = (s0 + s1) + (s2 + s3);
#pragma unroll
            for (int off = 16; off; off >>= 1)
                acc += __shfl_xor_sync(0xffffffffu, acc, off);
            if (lane == 0)
                out[((size_t)t * NE + n) * BATCH + bb] = acc + b2v;
        }
    }
}

// ---------------------------------------------------------------------------
// Launch: inputs in metadata order: targets, embeddings, W1, b1, W2, b2
// ---------------------------------------------------------------------------
extern "C" void kernel_launch(void* const* d_in, const int* in_sizes, int n_in,
                              void* d_out, int out_size)
{
    const float* targets    = (const float*)d_in[0];
    const float* embeddings = (const float*)d_in[1];
    const float* W1         = (const float*)d_in[2];
    const float* b1         = (const float*)d_in[3];
    const float* W2         = (const float*)d_in[4];
    const float* b2         = (const float*)d_in[5];
    float* out = (float*)d_out;

    const int fuse_smem = NE * VS * (int)sizeof(float);   // 98304
    cudaFuncSetAttribute(fuse_kernel,
                         cudaFuncAttributeMaxDynamicSharedMemorySize, fuse_smem);

    dim3 g1(VS / BN, M_ROWS / BM, 2);   // 8 x 24 x 2 = 384 blocks
    gemm_kernel<<<g1, 128>>>(targets, embeddings, W1, b1);

    dim3 g2(NT / TT, BATCH);            // 4 x 32 = 128 blocks
    fuse_kernel<<<g2, 256, fuse_smem>>>(W2, b2, out);
}

// round 5
// speedup vs baseline: 1.5374x; 1.5374x over previous
#include <cuda_runtime.h>
#include <cuda_bf16.h>
#include <cstdint>

// Problem constants
#define NT    48
#define NE    48
#define BATCH 32
#define VS    512
#define M_ROWS (NT * BATCH)   // 1536 rows per z

// ---------------------------------------------------------------------------
// Device-global scratch (no allocations allowed)
// ---------------------------------------------------------------------------
__device__ float g_A[M_ROWS * VS];            // ta + b1, [t*32+b][h]
__device__ float g_E[M_ROWS * VS];            // eb,      [n*32+b][h]
__device__ __nv_bfloat16 g_Xhi[2 * M_ROWS * VS];
__device__ __nv_bfloat16 g_Xlo[2 * M_ROWS * VS];
__device__ __nv_bfloat16 g_Whi[2 * VS * VS];
__device__ __nv_bfloat16 g_Wlo[2 * VS * VS];

// ---------------------------------------------------------------------------
// Kernel 0: fp32 -> bf16 hi/lo split of X (targets|embeddings) and W1 halves
// ---------------------------------------------------------------------------
#define NX4 (2 * M_ROWS * VS / 4)   // 393216 float4 of X
#define NW4 (2 * VS * VS / 4)       // 131072 float4 of W

__global__ __launch_bounds__(256) void split_kernel(
    const float* __restrict__ Tg, const float* __restrict__ Eg,
    const float* __restrict__ W1)
{
    const int gid = blockIdx.x * 256 + threadIdx.x;
    if (gid >= NX4 + NW4) return;

    float4 x;
    __nv_bfloat16* hi_arr;
    __nv_bfloat16* lo_arr;
    size_t didx;

    if (gid < NX4) {
        size_t e = (size_t)gid * 4;
        const float* src = (e < (size_t)M_ROWS * VS) ? (Tg + e)
                                                     : (Eg + e - (size_t)M_ROWS * VS);
        x = *(const float4*)src;
        hi_arr = g_Xhi; lo_arr = g_Xlo; didx = e;
    } else {
        size_t e = (size_t)(gid - NX4) * 4;
        int z = (int)(e / (VS * VS));
        size_t rem = e - (size_t)z * VS * VS;
        int h = (int)(rem / VS), v = (int)(rem % VS);
        x = *(const float4*)(W1 + (size_t)h * (2 * VS) + z * VS + v);
        hi_arr = g_Whi; lo_arr = g_Wlo; didx = e;
    }

    float xs[4] = {x.x, x.y, x.z, x.w};
    ushort hs[4], ls[4];
#pragma unroll
    for (int i = 0; i < 4; i++) {
        __nv_bfloat16 h = __float2bfloat16_rn(xs[i]);
        __nv_bfloat16 l = __float2bfloat16_rn(xs[i] - __bfloat162float(h));
        hs[i] = __bfloat16_as_ushort(h);
        ls[i] = __bfloat16_as_ushort(l);
    }
    uint2 hp, lp;
    hp.x = (uint32_t)hs[0] | ((uint32_t)hs[1] << 16);
    hp.y = (uint32_t)hs[2] | ((uint32_t)hs[3] << 16);
    lp.x = (uint32_t)ls[0] | ((uint32_t)ls[1] << 16);
    lp.y = (uint32_t)ls[2] | ((uint32_t)ls[3] << 16);
    *(uint2*)(hi_arr + didx) = hp;
    *(uint2*)(lo_arr + didx) = lp;
}

// ---------------------------------------------------------------------------
// Kernel 1: mma.sync bf16 3-pass GEMM (compute_103-legal, no tcgen05).
// C[m,h] = sum_v X[m,v]*W[h,v]  via  Xhi*Whi + Xhi*Wlo + Xlo*Whi
// CTA tile 128m x 128h, 8 warps (256 threads), warp tile 64x32 (m16n8k16).
// K chunks of 64, double-buffered smem, padded 144B rows (conflict-free).
// grid = (4 h-tiles, 12 m-tiles, 2 z).
// ---------------------------------------------------------------------------
#define NCHUNK 24                  // 3 passes * 8 chunks of K=64
#define ROW_B 144                  // 64 bf16 (128B) + 16B pad
#define BUF_BYTES (128 * ROW_B)    // 18432 per operand tile
#define GEMM_SMEM (4 * BUF_BYTES)  // 2 buffers * (A+B) = 73728

__global__ __launch_bounds__(256) void mma_gemm_kernel(const float* __restrict__ b1)
{
    extern __shared__ char smem[];
    const int tid  = threadIdx.x;
    const int lane = tid & 31;
    const int warp = tid >> 5;            // 0..7
    const int z  = blockIdx.z;
    const int m0 = blockIdx.y * 128;
    const int h0 = blockIdx.x * 128;
    float* __restrict__ C = z ? g_E : g_A;

    const int wm0 = (warp & 1) * 64;       // warp m offset: {0,64}
    const int wn0 = (warp >> 1) * 32;      // warp h offset: {0,32,64,96}
    const int lg  = lane >> 2;             // group id 0..7
    const int lq  = lane & 3;              // quad id 0..3

    float acc[4][4][4];
#pragma unroll
    for (int mi = 0; mi < 4; mi++)
#pragma unroll
        for (int ni = 0; ni < 4; ni++)
#pragma unroll
            for (int r = 0; r < 4; r++) acc[mi][ni][r] = 0.f;

    int4 ra[4], rb[4];   // 4 iterations x 256 threads = 1024 float4 per tile

    auto prefetch = [&](int c) {
        const int p  = c >> 3;             // pass 0,1,2
        const int k0 = (c & 7) * 64;
        const __nv_bfloat16* Ab = ((p == 2) ? g_Xlo : g_Xhi) + (size_t)z * M_ROWS * VS;
        const __nv_bfloat16* Bb = ((p == 1) ? g_Wlo : g_Whi) + (size_t)z * VS * VS;
#pragma unroll
        for (int i = 0; i < 4; i++) {
            const int id  = i * 256 + tid;
            const int row = id >> 3;
            const int cc  = (id & 7) * 8;  // bf16 offset in chunk row
            ra[i] = *(const int4*)(Ab + (size_t)(m0 + row) * VS + k0 + cc);
            rb[i] = *(const int4*)(Bb + (size_t)(h0 + row) * VS + k0 + cc);
        }
    };

    auto store_smem = [&](int c) {
        char* bufA = smem + (c & 1) * (2 * BUF_BYTES);
        char* bufB = bufA + BUF_BYTES;
#pragma unroll
        for (int i = 0; i < 4; i++) {
            const int id  = i * 256 + tid;
            const int row = id >> 3;
            const int cb  = (id & 7) * 16;
            *(int4*)(bufA + row * ROW_B + cb) = ra[i];
            *(int4*)(bufB + row * ROW_B + cb) = rb[i];
        }
    };

    auto compute = [&](int c) {
        const char* bufA = smem + (c & 1) * (2 * BUF_BYTES);
        const char* bufB = bufA + BUF_BYTES;
#pragma unroll
        for (int kc = 0; kc < 4; kc++) {
            uint32_t bfr[4][2];
#pragma unroll
            for (int ni = 0; ni < 4; ni++) {
                const char* p = bufB + (wn0 + ni * 8 + lg) * ROW_B + kc * 32 + lq * 4;
                bfr[ni][0] = *(const uint32_t*)p;          // k, k+1
                bfr[ni][1] = *(const uint32_t*)(p + 16);   // k+8, k+9
            }
#pragma unroll
            for (int mi = 0; mi < 4; mi++) {
                const char* p = bufA + (wm0 + mi * 16 + lg) * ROW_B + kc * 32 + lq * 4;
                uint32_t a0 = *(const uint32_t*)p;
                uint32_t a1 = *(const uint32_t*)(p + 8 * ROW_B);
                uint32_t a2 = *(const uint32_t*)(p + 16);
                uint32_t a3 = *(const uint32_t*)(p + 8 * ROW_B + 16);
#pragma unroll
                for (int ni = 0; ni < 4; ni++) {
                    asm volatile(
                        "mma.sync.aligned.m16n8k16.row.col.f32.bf16.bf16.f32 "
                        "{%0,%1,%2,%3}, {%4,%5,%6,%7}, {%8,%9}, {%0,%1,%2,%3};"
                        : "+f"(acc[mi][ni][0]), "+f"(acc[mi][ni][1]),
                          "+f"(acc[mi][ni][2]), "+f"(acc[mi][ni][3])
                        : "r"(a0), "r"(a1), "r"(a2), "r"(a3),
                          "r"(bfr[ni][0]), "r"(bfr[ni][1]));
                }
            }
        }
    };

    prefetch(0);
    store_smem(0);
    prefetch(1);
    __syncthreads();

    for (int c = 0; c < NCHUNK; c++) {
        if (c + 1 < NCHUNK) store_smem(c + 1);
        compute(c);
        if (c + 2 < NCHUNK) prefetch(c + 2);
        __syncthreads();
    }

    // Epilogue: bias (z==0) + float2 stores
#pragma unroll
    for (int mi = 0; mi < 4; mi++) {
        const int m = m0 + wm0 + mi * 16 + lg;
#pragma unroll
        for (int ni = 0; ni < 4; ni++) {
            const int h = h0 + wn0 + ni * 8 + lq * 2;
            float2 bias = make_float2(0.f, 0.f);
            if (z == 0) bias = *(const float2*)(b1 + h);
            float2 v0 = make_float2(acc[mi][ni][0] + bias.x, acc[mi][ni][1] + bias.y);
            float2 v1 = make_float2(acc[mi][ni][2] + bias.x, acc[mi][ni][3] + bias.y);
            *(float2*)(C + (size_t)m * VS + h)       = v0;
            *(float2*)(C + (size_t)(m + 8) * VS + h) = v1;
        }
    }
}

// ---------------------------------------------------------------------------
// Kernel 2: out[t,n,b] = sum_h w2[h]*tanh(A[t,b,h]+E[n,b,h]) + b2
// Block = (t-pair, b). 256 threads, E straight from L2. MUFU-bound.
// ---------------------------------------------------------------------------
__device__ __forceinline__ float tanh_fast(float x) {
    float y;
    asm("tanh.approx.f32 %0, %1;" : "=f"(y) : "f"(x));
    return y;
}

__global__ __launch_bounds__(256) void fuse_kernel(
    const float* __restrict__ W2, const float* __restrict__ b2,
    float* __restrict__ out)
{
    const int bb = blockIdx.y;
    const int t0 = blockIdx.x * 2;
    const int warp = threadIdx.x >> 5;
    const int lane = threadIdx.x & 31;

    const float4* W4 = (const float4*)W2;
    float4 w[4];
#pragma unroll
    for (int j = 0; j < 4; j++) w[j] = __ldg(&W4[lane + 32 * j]);

    float4 a0[4], a1[4];
    {
        const float4* A0 = (const float4*)(g_A + ((size_t)(t0 * BATCH + bb)) * VS);
        const float4* A1 = (const float4*)(g_A + ((size_t)((t0 + 1) * BATCH + bb)) * VS);
#pragma unroll
        for (int j = 0; j < 4; j++) { a0[j] = A0[lane + 32 * j]; a1[j] = A1[lane + 32 * j]; }
    }
    const float b2v = __ldg(b2);

    for (int n = warp; n < NE; n += 8) {
        const float4* E4 = (const float4*)(g_E + ((size_t)(n * BATCH + bb)) * VS);
        float s0 = 0.f, s1 = 0.f;
#pragma unroll
        for (int j = 0; j < 4; j++) {
            float4 e = __ldg(&E4[lane + 32 * j]);
            s0 = fmaf(w[j].x, tanh_fast(a0[j].x + e.x), s0);
            s1 = fmaf(w[j].x, tanh_fast(a1[j].x + e.x), s1);
            s0 = fmaf(w[j].y, tanh_fast(a0[j].y + e.y), s0);
            s1 = fmaf(w[j].y, tanh_fast(a1[j].y + e.y), s1);
            s0 = fmaf(w[j].z, tanh_fast(a0[j].z + e.z), s0);
            s1 = fmaf(w[j].z, tanh_fast(a1[j].z + e.z), s1);
            s0 = fmaf(w[j].w, tanh_fast(a0[j].w + e.w), s0);
            s1 = fmaf(w[j].w, tanh_fast(a1[j].w + e.w), s1);
        }
#pragma unroll
        for (int off = 16; off; off >>= 1) {
            s0 += __shfl_xor_sync(0xffffffffu, s0, off);
            s1 += __shfl_xor_sync(0xffffffffu, s1, off);
        }
        if (lane == 0) {
            out[((size_t)t0 * NE + n) * BATCH + bb]       = s0 + b2v;
            out[((size_t)(t0 + 1) * NE + n) * BATCH + bb] = s1 + b2v;
        }
    }
}

// ---------------------------------------------------------------------------
// Launch: inputs in metadata order: targets, embeddings, W1, b1, W2, b2
// ---------------------------------------------------------------------------
extern "C" void kernel_launch(void* const* d_in, const int* in_sizes, int n_in,
                              void* d_out, int out_size)
{
    const float* targets    = (const float*)d_in[0];
    const float* embeddings = (const float*)d_in[1];
    const float* W1         = (const float*)d_in[2];
    const float* b1         = (const float*)d_in[3];
    const float* W2         = (const float*)d_in[4];
    const float* b2         = (const float*)d_in[5];
    float* out = (float*)d_out;

    cudaFuncSetAttribute(mma_gemm_kernel,
                         cudaFuncAttributeMaxDynamicSharedMemorySize, GEMM_SMEM);

    const int nsplit = (NX4 + NW4 + 255) / 256;   // 2048 blocks
    split_kernel<<<nsplit, 256>>>(targets, embeddings, W1);

    dim3 gg(4, 12, 2);   // h-tiles, m-tiles, z
    mma_gemm_kernel<<<gg, 256, GEMM_SMEM>>>(b1);

    dim3 gf(NT / 2, BATCH);   // 24 x 32
    fuse_kernel<<<gf, 256>>>(W2, b2, out);
}

// round 6
// speedup vs baseline: 1.6653x; 1.0832x over previous
#include <cuda_runtime.h>
#include <cuda_bf16.h>
#include <cstdint>

// Problem constants
#define NT    48
#define NE    48
#define BATCH 32
#define VS    512
#define M_ROWS (NT * BATCH)   // 1536 rows per z

// ---------------------------------------------------------------------------
// Device-global scratch (no allocations allowed)
// ---------------------------------------------------------------------------
__device__ float g_A[M_ROWS * VS];            // ta + b1, [t*32+b][h]
__device__ float g_E[M_ROWS * VS];            // eb,      [n*32+b][h]
__device__ __nv_bfloat16 g_Xhi[2 * M_ROWS * VS];
__device__ __nv_bfloat16 g_Xlo[2 * M_ROWS * VS];
__device__ __nv_bfloat16 g_Whi[2 * VS * VS];
__device__ __nv_bfloat16 g_Wlo[2 * VS * VS];

__device__ __forceinline__ uint32_t smem_u32(const void* p) {
    uint32_t a;
    asm("{ .reg .u64 t; cvta.to.shared.u64 t, %1; cvt.u32.u64 %0, t; }"
        : "=r"(a) : "l"(p));
    return a;
}

// ---------------------------------------------------------------------------
// Kernel 0: fp32 -> bf16 hi/lo split of X (targets|embeddings) and W1 halves
// ---------------------------------------------------------------------------
#define NX4 (2 * M_ROWS * VS / 4)   // 393216 float4 of X
#define NW4 (2 * VS * VS / 4)       // 131072 float4 of W

__global__ __launch_bounds__(256) void split_kernel(
    const float* __restrict__ Tg, const float* __restrict__ Eg,
    const float* __restrict__ W1)
{
    const int gid = blockIdx.x * 256 + threadIdx.x;
    if (gid >= NX4 + NW4) return;

    float4 x;
    __nv_bfloat16* hi_arr;
    __nv_bfloat16* lo_arr;
    size_t didx;

    if (gid < NX4) {
        size_t e = (size_t)gid * 4;
        const float* src = (e < (size_t)M_ROWS * VS) ? (Tg + e)
                                                     : (Eg + e - (size_t)M_ROWS * VS);
        x = *(const float4*)src;
        hi_arr = g_Xhi; lo_arr = g_Xlo; didx = e;
    } else {
        size_t e = (size_t)(gid - NX4) * 4;
        int z = (int)(e / (VS * VS));
        size_t rem = e - (size_t)z * VS * VS;
        int h = (int)(rem / VS), v = (int)(rem % VS);
        x = *(const float4*)(W1 + (size_t)h * (2 * VS) + z * VS + v);
        hi_arr = g_Whi; lo_arr = g_Wlo; didx = e;
    }

    float xs[4] = {x.x, x.y, x.z, x.w};
    ushort hs[4], ls[4];
#pragma unroll
    for (int i = 0; i < 4; i++) {
        __nv_bfloat16 h = __float2bfloat16_rn(xs[i]);
        __nv_bfloat16 l = __float2bfloat16_rn(xs[i] - __bfloat162float(h));
        hs[i] = __bfloat16_as_ushort(h);
        ls[i] = __bfloat16_as_ushort(l);
    }
    uint2 hp, lp;
    hp.x = (uint32_t)hs[0] | ((uint32_t)hs[1] << 16);
    hp.y = (uint32_t)hs[2] | ((uint32_t)hs[3] << 16);
    lp.x = (uint32_t)ls[0] | ((uint32_t)ls[1] << 16);
    lp.y = (uint32_t)ls[2] | ((uint32_t)ls[3] << 16);
    *(uint2*)(hi_arr + didx) = hp;
    *(uint2*)(lo_arr + didx) = lp;
}

// ---------------------------------------------------------------------------
// Kernel 1: mma.sync bf16 3-pass GEMM with cp.async + ldmatrix.
// C[m,h] = sum_v X[m,v]*W[h,v]  via  Xhi*Whi + Xhi*Wlo + Xlo*Whi
// CTA tile 128m x 128h, 8 warps, warp tile 64x32 (m16n8k16).
// K chunks of 128, double-buffered; 272B-padded rows (conflict-free for
// cp.async stores and all ldmatrix phases: stride 17 x 16B).
// grid = (4 h-tiles, 12 m-tiles, 2 z), 256 threads.
// ---------------------------------------------------------------------------
#define NCHUNK 12                  // 3 passes * 4 chunks of K=128
#define ROW_B 272                  // 128 bf16 (256B) + 16B pad
#define ABUF  (128 * ROW_B)        // 34816 per operand tile
#define STAGE (2 * ABUF)           // A + B
#define GEMM_SMEM (2 * STAGE)      // double buffer = 139264

__device__ __forceinline__ void cp16(uint32_t dst, const void* src) {
    asm volatile("cp.async.cg.shared.global [%0], [%1], 16;"
                 :: "r"(dst), "l"(src));
}
__device__ __forceinline__ void ldsm4(uint32_t* f, uint32_t addr) {
    asm volatile("ldmatrix.sync.aligned.m8n8.x4.shared.b16 {%0,%1,%2,%3}, [%4];"
                 : "=r"(f[0]), "=r"(f[1]), "=r"(f[2]), "=r"(f[3]) : "r"(addr));
}

__global__ __launch_bounds__(256) void mma_gemm_kernel(const float* __restrict__ b1)
{
    extern __shared__ char smem[];
    const uint32_t sbase = smem_u32(smem);
    const int tid  = threadIdx.x;
    const int lane = tid & 31;
    const int warp = tid >> 5;            // 0..7
    const int z  = blockIdx.z;
    const int m0 = blockIdx.y * 128;
    const int h0 = blockIdx.x * 128;
    float* __restrict__ C = z ? g_E : g_A;

    const int wm0 = (warp & 1) * 64;       // warp m offset: {0,64}
    const int wn0 = (warp >> 1) * 32;      // warp h offset: {0,32,64,96}
    const int lg  = lane >> 2;             // group id 0..7
    const int lq  = lane & 3;              // quad id 0..3

    // ldmatrix per-lane base offsets (within a stage)
    const int m4 = lane >> 3;              // matrix index 0..3
    const int r8 = lane & 7;               // row within 8x8 matrix
    const uint32_t aOff = (uint32_t)((wm0 + (m4 & 1) * 8 + r8) * ROW_B + (m4 >> 1) * 16);
    const uint32_t bOff = (uint32_t)((wn0 + (m4 >> 1) * 8 + r8) * ROW_B + (m4 & 1) * 16);

    float acc[4][4][4];
#pragma unroll
    for (int mi = 0; mi < 4; mi++)
#pragma unroll
        for (int ni = 0; ni < 4; ni++)
#pragma unroll
            for (int r = 0; r < 4; r++) acc[mi][ni][r] = 0.f;

    // cp.async load mapping: 2048 int4 per operand tile, 8 per thread
    const int lrow = tid >> 4;             // base row (step 16)
    const int lcol = tid & 15;             // int4 within 256B row

    auto issue = [&](int c) {
        const int p  = c >> 2;             // pass 0,1,2
        const int k0 = (c & 3) * 128;
        const __nv_bfloat16* Ab = ((p == 2) ? g_Xlo : g_Xhi) + (size_t)z * M_ROWS * VS;
        const __nv_bfloat16* Bb = ((p == 1) ? g_Wlo : g_Whi) + (size_t)z * VS * VS;
        const uint32_t sA = sbase + (c & 1) * STAGE;
        const uint32_t sB = sA + ABUF;
#pragma unroll
        for (int i = 0; i < 8; i++) {
            const int row = i * 16 + lrow;
            const uint32_t d = (uint32_t)(row * ROW_B + lcol * 16);
            cp16(sA + d, Ab + (size_t)(m0 + row) * VS + k0 + lcol * 8);
            cp16(sB + d, Bb + (size_t)(h0 + row) * VS + k0 + lcol * 8);
        }
        asm volatile("cp.async.commit_group;");
    };

    auto compute = [&](int c) {
        const uint32_t sA = sbase + (c & 1) * STAGE + aOff;
        const uint32_t sB = sbase + (c & 1) * STAGE + ABUF + bOff;
#pragma unroll
        for (int kc = 0; kc < 8; kc++) {
            uint32_t bf[2][4];
            ldsm4(bf[0], sB + kc * 32);
            ldsm4(bf[1], sB + 16 * ROW_B + kc * 32);
#pragma unroll
            for (int mi = 0; mi < 4; mi++) {
                uint32_t a[4];
                ldsm4(a, sA + mi * 16 * ROW_B + kc * 32);
#pragma unroll
                for (int ni = 0; ni < 4; ni++) {
                    asm volatile(
                        "mma.sync.aligned.m16n8k16.row.col.f32.bf16.bf16.f32 "
                        "{%0,%1,%2,%3}, {%4,%5,%6,%7}, {%8,%9}, {%0,%1,%2,%3};"
                        : "+f"(acc[mi][ni][0]), "+f"(acc[mi][ni][1]),
                          "+f"(acc[mi][ni][2]), "+f"(acc[mi][ni][3])
                        : "r"(a[0]), "r"(a[1]), "r"(a[2]), "r"(a[3]),
                          "r"(bf[ni >> 1][(ni & 1) * 2]),
                          "r"(bf[ni >> 1][(ni & 1) * 2 + 1]));
                }
            }
        }
    };

    issue(0);
    for (int c = 0; c < NCHUNK; c++) {
        if (c + 1 < NCHUNK) {
            issue(c + 1);
            asm volatile("cp.async.wait_group 1;");
        } else {
            asm volatile("cp.async.wait_group 0;");
        }
        __syncthreads();
        compute(c);
        __syncthreads();
    }

    // Epilogue: bias (z==0) + float2 stores
#pragma unroll
    for (int mi = 0; mi < 4; mi++) {
        const int m = m0 + wm0 + mi * 16 + lg;
#pragma unroll
        for (int ni = 0; ni < 4; ni++) {
            const int h = h0 + wn0 + ni * 8 + lq * 2;
            float2 bias = make_float2(0.f, 0.f);
            if (z == 0) bias = *(const float2*)(b1 + h);
            float2 v0 = make_float2(acc[mi][ni][0] + bias.x, acc[mi][ni][1] + bias.y);
            float2 v1 = make_float2(acc[mi][ni][2] + bias.x, acc[mi][ni][3] + bias.y);
            *(float2*)(C + (size_t)m * VS + h)       = v0;
            *(float2*)(C + (size_t)(m + 8) * VS + h) = v1;
        }
    }
}

// ---------------------------------------------------------------------------
// Kernel 2: out[t,n,b] = sum_h w2[h]*tanh(A[t,b,h]+E[n,b,h]) + b2
// Block = (4 targets, b). 256 threads, E from L2, 16 MUFU chains per e-load.
// ---------------------------------------------------------------------------
#define TPB 4

__device__ __forceinline__ float tanh_fast(float x) {
    float y;
    asm("tanh.approx.f32 %0, %1;" : "=f"(y) : "f"(x));
    return y;
}

__global__ __launch_bounds__(256) void fuse_kernel(
    const float* __restrict__ W2, const float* __restrict__ b2,
    float* __restrict__ out)
{
    const int bb = blockIdx.y;
    const int t0 = blockIdx.x * TPB;
    const int warp = threadIdx.x >> 5;
    const int lane = threadIdx.x & 31;

    const float4* W4 = (const float4*)W2;
    float4 w[4];
#pragma unroll
    for (int j = 0; j < 4; j++) w[j] = __ldg(&W4[lane + 32 * j]);

    float4 a[TPB][4];
#pragma unroll
    for (int t = 0; t < TPB; t++) {
        const float4* A4 = (const float4*)(g_A + ((size_t)((t0 + t) * BATCH + bb)) * VS);
#pragma unroll
        for (int j = 0; j < 4; j++) a[t][j] = A4[lane + 32 * j];
    }
    const float b2v = __ldg(b2);

    for (int n = warp; n < NE; n += 8) {
        const float4* E4 = (const float4*)(g_E + ((size_t)(n * BATCH + bb)) * VS);
        float s[TPB] = {0.f, 0.f, 0.f, 0.f};
#pragma unroll
        for (int j = 0; j < 4; j++) {
            float4 e = __ldg(&E4[lane + 32 * j]);
#pragma unroll
            for (int t = 0; t < TPB; t++) {
                s[t] = fmaf(w[j].x, tanh_fast(a[t][j].x + e.x), s[t]);
                s[t] = fmaf(w[j].y, tanh_fast(a[t][j].y + e.y), s[t]);
                s[t] = fmaf(w[j].z, tanh_fast(a[t][j].z + e.z), s[t]);
                s[t] = fmaf(w[j].w, tanh_fast(a[t][j].w + e.w), s[t]);
            }
        }
#pragma unroll
        for (int off = 16; off; off >>= 1)
#pragma unroll
            for (int t = 0; t < TPB; t++)
                s[t] += __shfl_xor_sync(0xffffffffu, s[t], off);
        if (lane == 0) {
#pragma unroll
            for (int t = 0; t < TPB; t++)
                out[((size_t)(t0 + t) * NE + n) * BATCH + bb] = s[t] + b2v;
        }
    }
}

// ---------------------------------------------------------------------------
// Launch: inputs in metadata order: targets, embeddings, W1, b1, W2, b2
// ---------------------------------------------------------------------------
extern "C" void kernel_launch(void* const* d_in, const int* in_sizes, int n_in,
                              void* d_out, int out_size)
{
    const float* targets    = (const float*)d_in[0];
    const float* embeddings = (const float*)d_in[1];
    const float* W1         = (const float*)d_in[2];
    const float* b1         = (const float*)d_in[3];
    const float* W2         = (const float*)d_in[4];
    const float* b2         = (const float*)d_in[5];
    float* out = (float*)d_out;

    cudaFuncSetAttribute(mma_gemm_kernel,
                         cudaFuncAttributeMaxDynamicSharedMemorySize, GEMM_SMEM);

    const int nsplit = (NX4 + NW4 + 255) / 256;   // 2048 blocks
    split_kernel<<<nsplit, 256>>>(targets, embeddings, W1);

    dim3 gg(4, 12, 2);   // h-tiles, m-tiles, z
    mma_gemm_kernel<<<gg, 256, GEMM_SMEM>>>(b1);

    dim3 gf(NT / TPB, BATCH);   // 12 x 32
    fuse_kernel<<<gf, 256>>>(W2, b2, out);
}

// round 7
// speedup vs baseline: 2.1605x; 1.2974x over previous
#include <cuda_runtime.h>
#include <cuda_fp16.h>
#include <cstdint>

// Problem constants
#define NT    48
#define NE    48
#define BATCH 32
#define VS    512
#define M_ROWS (NT * BATCH)   // 1536 rows per z

// ---------------------------------------------------------------------------
// Device-global scratch (no allocations allowed)
// ---------------------------------------------------------------------------
__device__ float g_A[M_ROWS * VS];            // ta + b1, [t*32+b][h]
__device__ float g_E[M_ROWS * VS];            // eb,      [n*32+b][h]
__device__ __half g_Xh[2 * M_ROWS * VS];      // fp16 hi of X (targets|emb)
__device__ __half g_Xl[2 * M_ROWS * VS];      // fp16 lo of X
__device__ __half g_Wh[2 * VS * VS];          // fp16 of W1 halves [z][h][v]

__device__ __forceinline__ uint32_t smem_u32(const void* p) {
    uint32_t a;
    asm("{ .reg .u64 t; cvta.to.shared.u64 t, %1; cvt.u32.u64 %0, t; }"
        : "=r"(a) : "l"(p));
    return a;
}

// ---------------------------------------------------------------------------
// Kernel 0: fp32 -> fp16 hi/lo split of X; fp16 convert of W1 halves
// ---------------------------------------------------------------------------
#define NX4 (2 * M_ROWS * VS / 4)   // 393216 float4 of X
#define NW4 (2 * VS * VS / 4)       // 131072 float4 of W

__global__ __launch_bounds__(256) void split_kernel(
    const float* __restrict__ Tg, const float* __restrict__ Eg,
    const float* __restrict__ W1)
{
    const int gid = blockIdx.x * 256 + threadIdx.x;
    if (gid >= NX4 + NW4) return;

    if (gid < NX4) {
        size_t e = (size_t)gid * 4;
        const float* src = (e < (size_t)M_ROWS * VS) ? (Tg + e)
                                                     : (Eg + e - (size_t)M_ROWS * VS);
        float4 x = *(const float4*)src;
        float xs[4] = {x.x, x.y, x.z, x.w};
        ushort hs[4], ls[4];
#pragma unroll
        for (int i = 0; i < 4; i++) {
            __half h = __float2half_rn(xs[i]);
            __half l = __float2half_rn(xs[i] - __half2float(h));
            hs[i] = __half_as_ushort(h);
            ls[i] = __half_as_ushort(l);
        }
        uint2 hp, lp;
        hp.x = (uint32_t)hs[0] | ((uint32_t)hs[1] << 16);
        hp.y = (uint32_t)hs[2] | ((uint32_t)hs[3] << 16);
        lp.x = (uint32_t)ls[0] | ((uint32_t)ls[1] << 16);
        lp.y = (uint32_t)ls[2] | ((uint32_t)ls[3] << 16);
        *(uint2*)(g_Xh + e) = hp;
        *(uint2*)(g_Xl + e) = lp;
    } else {
        size_t e = (size_t)(gid - NX4) * 4;
        int z = (int)(e >> 18);              // / (VS*VS)
        size_t rem = e & ((1u << 18) - 1);
        int h = (int)(rem >> 9), v = (int)(rem & 511);
        float4 x = *(const float4*)(W1 + (size_t)h * (2 * VS) + z * VS + v);
        float xs[4] = {x.x, x.y, x.z, x.w};
        ushort hs[4];
#pragma unroll
        for (int i = 0; i < 4; i++)
            hs[i] = __half_as_ushort(__float2half_rn(xs[i]));
        uint2 hp;
        hp.x = (uint32_t)hs[0] | ((uint32_t)hs[1] << 16);
        hp.y = (uint32_t)hs[2] | ((uint32_t)hs[3] << 16);
        *(uint2*)(g_Wh + e) = hp;
    }
}

// ---------------------------------------------------------------------------
// Kernel 1: mma.sync fp16 2-pass GEMM (Xhi*Wh + Xlo*Wh), fp32 accumulate.
// CTA tile 128m x 128h, 8 warps, warp tile 64x32 (m16n8k16.f16).
// K chunks of 128; stage = {Xhi, Xlo, Wh} tiles; double-buffered cp.async.
// B fragments shared across both passes. grid = (4 h, 12 m, 2 z), 256 thr.
// ---------------------------------------------------------------------------
#define NCHUNK 4                   // 4 chunks of K=128 (x 2 passes inside)
#define ROW_B 272                  // 128 fp16 (256B) + 16B pad
#define TILE_B (128 * ROW_B)       // 34816 per tile
#define STAGE (3 * TILE_B)         // Xhi + Xlo + Wh = 104448
#define GEMM_SMEM (2 * STAGE)      // 208896

__device__ __forceinline__ void cp16(uint32_t dst, const void* src) {
    asm volatile("cp.async.cg.shared.global [%0], [%1], 16;"
                 :: "r"(dst), "l"(src));
}
__device__ __forceinline__ void ldsm4(uint32_t* f, uint32_t addr) {
    asm volatile("ldmatrix.sync.aligned.m8n8.x4.shared.b16 {%0,%1,%2,%3}, [%4];"
                 : "=r"(f[0]), "=r"(f[1]), "=r"(f[2]), "=r"(f[3]) : "r"(addr));
}
#define MMA_F16(acc, a, b0, b1)                                               \
    asm volatile(                                                             \
        "mma.sync.aligned.m16n8k16.row.col.f32.f16.f16.f32 "                  \
        "{%0,%1,%2,%3}, {%4,%5,%6,%7}, {%8,%9}, {%0,%1,%2,%3};"               \
        : "+f"((acc)[0]), "+f"((acc)[1]), "+f"((acc)[2]), "+f"((acc)[3])      \
        : "r"((a)[0]), "r"((a)[1]), "r"((a)[2]), "r"((a)[3]),                 \
          "r"(b0), "r"(b1))

__global__ __launch_bounds__(256) void mma_gemm_kernel(const float* __restrict__ b1)
{
    extern __shared__ char smem[];
    const uint32_t sbase = smem_u32(smem);
    const int tid  = threadIdx.x;
    const int lane = tid & 31;
    const int warp = tid >> 5;            // 0..7
    const int z  = blockIdx.z;
    const int m0 = blockIdx.y * 128;
    const int h0 = blockIdx.x * 128;
    float* __restrict__ C = z ? g_E : g_A;

    const int wm0 = (warp & 1) * 64;       // warp m offset: {0,64}
    const int wn0 = (warp >> 1) * 32;      // warp h offset: {0,32,64,96}
    const int lg  = lane >> 2;             // group id 0..7
    const int lq  = lane & 3;              // quad id 0..3

    // ldmatrix per-lane base offsets (within a tile)
    const int m4 = lane >> 3;
    const int r8 = lane & 7;
    const uint32_t aOff = (uint32_t)((wm0 + (m4 & 1) * 8 + r8) * ROW_B + (m4 >> 1) * 16);
    const uint32_t bOff = (uint32_t)((wn0 + (m4 >> 1) * 8 + r8) * ROW_B + (m4 & 1) * 16);

    float acc[4][4][4];
#pragma unroll
    for (int mi = 0; mi < 4; mi++)
#pragma unroll
        for (int ni = 0; ni < 4; ni++)
#pragma unroll
            for (int r = 0; r < 4; r++) acc[mi][ni][r] = 0.f;

    const int lrow = tid >> 4;             // 0..15
    const int lcol = tid & 15;             // int4 within 256B row

    const __half* Xh = g_Xh + (size_t)z * M_ROWS * VS;
    const __half* Xl = g_Xl + (size_t)z * M_ROWS * VS;
    const __half* Wh = g_Wh + (size_t)z * VS * VS;

    auto issue = [&](int c) {
        const int k0 = c * 128;
        const uint32_t s0 = sbase + (c & 1) * STAGE;
#pragma unroll
        for (int i = 0; i < 8; i++) {
            const int row = i * 16 + lrow;
            const uint32_t d = (uint32_t)(row * ROW_B + lcol * 16);
            cp16(s0 + d,              Xh + (size_t)(m0 + row) * VS + k0 + lcol * 8);
            cp16(s0 + TILE_B + d,     Xl + (size_t)(m0 + row) * VS + k0 + lcol * 8);
            cp16(s0 + 2 * TILE_B + d, Wh + (size_t)(h0 + row) * VS + k0 + lcol * 8);
        }
        asm volatile("cp.async.commit_group;");
    };

    auto compute = [&](int c) {
        const uint32_t s0  = sbase + (c & 1) * STAGE;
        const uint32_t aHi = s0 + aOff;
        const uint32_t aLo = s0 + TILE_B + aOff;
        const uint32_t sB  = s0 + 2 * TILE_B + bOff;
#pragma unroll
        for (int kc = 0; kc < 8; kc++) {
            uint32_t bf[2][4];
            ldsm4(bf[0], sB + kc * 32);
            ldsm4(bf[1], sB + 16 * ROW_B + kc * 32);
#pragma unroll
            for (int mi = 0; mi < 4; mi++) {
                uint32_t a[4];
                ldsm4(a, aHi + mi * 16 * ROW_B + kc * 32);
#pragma unroll
                for (int ni = 0; ni < 4; ni++)
                    MMA_F16(acc[mi][ni], a,
                            bf[ni >> 1][(ni & 1) * 2], bf[ni >> 1][(ni & 1) * 2 + 1]);
                ldsm4(a, aLo + mi * 16 * ROW_B + kc * 32);
#pragma unroll
                for (int ni = 0; ni < 4; ni++)
                    MMA_F16(acc[mi][ni], a,
                            bf[ni >> 1][(ni & 1) * 2], bf[ni >> 1][(ni & 1) * 2 + 1]);
            }
        }
    };

    issue(0);
    for (int c = 0; c < NCHUNK; c++) {
        if (c + 1 < NCHUNK) {
            issue(c + 1);
            asm volatile("cp.async.wait_group 1;");
        } else {
            asm volatile("cp.async.wait_group 0;");
        }
        __syncthreads();
        compute(c);
        __syncthreads();
    }

    // Epilogue: bias (z==0) + float2 stores
#pragma unroll
    for (int mi = 0; mi < 4; mi++) {
        const int m = m0 + wm0 + mi * 16 + lg;
#pragma unroll
        for (int ni = 0; ni < 4; ni++) {
            const int h = h0 + wn0 + ni * 8 + lq * 2;
            float2 bias = make_float2(0.f, 0.f);
            if (z == 0) bias = *(const float2*)(b1 + h);
            float2 v0 = make_float2(acc[mi][ni][0] + bias.x, acc[mi][ni][1] + bias.y);
            float2 v1 = make_float2(acc[mi][ni][2] + bias.x, acc[mi][ni][3] + bias.y);
            *(float2*)(C + (size_t)m * VS + h)       = v0;
            *(float2*)(C + (size_t)(m + 8) * VS + h) = v1;
        }
    }
}

// ---------------------------------------------------------------------------
// Kernel 2: out[t,n,b] = sum_h w2[h]*tanh(A[t,b,h]+E[n,b,h]) + b2
// Block = (4 targets, b). 256 threads, E from L2, 16 MUFU chains per e-load.
// ---------------------------------------------------------------------------
#define TPB 4

__device__ __forceinline__ float tanh_fast(float x) {
    float y;
    asm("tanh.approx.f32 %0, %1;" : "=f"(y) : "f"(x));
    return y;
}

__global__ __launch_bounds__(256) void fuse_kernel(
    const float* __restrict__ W2, const float* __restrict__ b2,
    float* __restrict__ out)
{
    const int bb = blockIdx.y;
    const int t0 = blockIdx.x * TPB;
    const int warp = threadIdx.x >> 5;
    const int lane = threadIdx.x & 31;

    const float4* W4 = (const float4*)W2;
    float4 w[4];
#pragma unroll
    for (int j = 0; j < 4; j++) w[j] = __ldg(&W4[lane + 32 * j]);

    float4 a[TPB][4];
#pragma unroll
    for (int t = 0; t < TPB; t++) {
        const float4* A4 = (const float4*)(g_A + ((size_t)((t0 + t) * BATCH + bb)) * VS);
#pragma unroll
        for (int j = 0; j < 4; j++) a[t][j] = A4[lane + 32 * j];
    }
    const float b2v = __ldg(b2);

    for (int n = warp; n < NE; n += 8) {
        const float4* E4 = (const float4*)(g_E + ((size_t)(n * BATCH + bb)) * VS);
        float s[TPB] = {0.f, 0.f, 0.f, 0.f};
#pragma unroll
        for (int j = 0; j < 4; j++) {
            float4 e = __ldg(&E4[lane + 32 * j]);
#pragma unroll
            for (int t = 0; t < TPB; t++) {
                s[t] = fmaf(w[j].x, tanh_fast(a[t][j].x + e.x), s[t]);
                s[t] = fmaf(w[j].y, tanh_fast(a[t][j].y + e.y), s[t]);
                s[t] = fmaf(w[j].z, tanh_fast(a[t][j].z + e.z), s[t]);
                s[t] = fmaf(w[j].w, tanh_fast(a[t][j].w + e.w), s[t]);
            }
        }
#pragma unroll
        for (int off = 16; off; off >>= 1)
#pragma unroll
            for (int t = 0; t < TPB; t++)
                s[t] += __shfl_xor_sync(0xffffffffu, s[t], off);
        if (lane == 0) {
#pragma unroll
            for (int t = 0; t < TPB; t++)
                out[((size_t)(t0 + t) * NE + n) * BATCH + bb] = s[t] + b2v;
        }
    }
}

// ---------------------------------------------------------------------------
// Launch: inputs in metadata order: targets, embeddings, W1, b1, W2, b2
// ---------------------------------------------------------------------------
extern "C" void kernel_launch(void* const* d_in, const int* in_sizes, int n_in,
                              void* d_out, int out_size)
{
    const float* targets    = (const float*)d_in[0];
    const float* embeddings = (const float*)d_in[1];
    const float* W1         = (const float*)d_in[2];
    const float* b1         = (const float*)d_in[3];
    const float* W2         = (const float*)d_in[4];
    const float* b2         = (const float*)d_in[5];
    float* out = (float*)d_out;

    cudaFuncSetAttribute(mma_gemm_kernel,
                         cudaFuncAttributeMaxDynamicSharedMemorySize, GEMM_SMEM);

    const int nsplit = (NX4 + NW4 + 255) / 256;   // 2048 blocks
    split_kernel<<<nsplit, 256>>>(targets, embeddings, W1);

    dim3 gg(4, 12, 2);   // h-tiles, m-tiles, z
    mma_gemm_kernel<<<gg, 256, GEMM_SMEM>>>(b1);

    dim3 gf(NT / TPB, BATCH);   // 12 x 32
    fuse_kernel<<<gf, 256>>>(W2, b2, out);
}

// round 8
// speedup vs baseline: 2.6129x; 1.2094x over previous
#include <cuda_runtime.h>
#include <cuda_fp16.h>
#include <cstdint>

// Problem constants
#define NT    48
#define NE    48
#define BATCH 32
#define VS    512
#define M_ROWS (NT * BATCH)   // 1536 rows per z

// ---------------------------------------------------------------------------
// Device-global scratch (no allocations allowed)
// ---------------------------------------------------------------------------
__device__ float g_A[M_ROWS * VS];            // ta + b1, [t*32+b][h]
__device__ float g_E[M_ROWS * VS];            // eb,      [n*32+b][h]
__device__ __half g_Xh[2 * M_ROWS * VS];      // fp16 of X (targets|emb)
__device__ __half g_Wh[2 * VS * VS];          // fp16 of W1 halves [z][h][v]

__device__ __forceinline__ uint32_t smem_u32(const void* p) {
    uint32_t a;
    asm("{ .reg .u64 t; cvta.to.shared.u64 t, %1; cvt.u32.u64 %0, t; }"
        : "=r"(a) : "l"(p));
    return a;
}

// ---------------------------------------------------------------------------
// Kernel 0: fp32 -> fp16 convert of X (targets|embeddings) and W1 halves
// ---------------------------------------------------------------------------
#define NX4 (2 * M_ROWS * VS / 4)   // 393216 float4 of X
#define NW4 (2 * VS * VS / 4)       // 131072 float4 of W

__global__ __launch_bounds__(256) void split_kernel(
    const float* __restrict__ Tg, const float* __restrict__ Eg,
    const float* __restrict__ W1)
{
    const int gid = blockIdx.x * 256 + threadIdx.x;
    if (gid >= NX4 + NW4) return;

    float4 x;
    __half* dst;
    size_t e;

    if (gid < NX4) {
        e = (size_t)gid * 4;
        const float* src = (e < (size_t)M_ROWS * VS) ? (Tg + e)
                                                     : (Eg + e - (size_t)M_ROWS * VS);
        x = *(const float4*)src;
        dst = g_Xh;
    } else {
        e = (size_t)(gid - NX4) * 4;
        int z = (int)(e >> 18);              // / (VS*VS)
        size_t rem = e & ((1u << 18) - 1);
        int h = (int)(rem >> 9), v = (int)(rem & 511);
        x = *(const float4*)(W1 + (size_t)h * (2 * VS) + z * VS + v);
        dst = g_Wh;
    }

    float xs[4] = {x.x, x.y, x.z, x.w};
    ushort hs[4];
#pragma unroll
    for (int i = 0; i < 4; i++)
        hs[i] = __half_as_ushort(__float2half_rn(xs[i]));
    uint2 hp;
    hp.x = (uint32_t)hs[0] | ((uint32_t)hs[1] << 16);
    hp.y = (uint32_t)hs[2] | ((uint32_t)hs[3] << 16);
    *(uint2*)(dst + e) = hp;
}

// ---------------------------------------------------------------------------
// Kernel 1: mma.sync fp16 single-pass GEMM (fp16(X) * fp16(W)), fp32 accum.
// CTA tile 128m x 128h, 8 warps, warp tile 64x32 (m16n8k16.f16).
// K chunks of 128; stage = {Xh, Wh}; double-buffered cp.async + ldmatrix.
// grid = (4 h, 12 m, 2 z), 256 threads.
// ---------------------------------------------------------------------------
#define NCHUNK 4                   // 4 chunks of K=128
#define ROW_B 272                  // 128 fp16 (256B) + 16B pad
#define TILE_B (128 * ROW_B)       // 34816 per tile
#define STAGE (2 * TILE_B)         // Xh + Wh = 69632
#define GEMM_SMEM (2 * STAGE)      // 139264

__device__ __forceinline__ void cp16(uint32_t dst, const void* src) {
    asm volatile("cp.async.cg.shared.global [%0], [%1], 16;"
                 :: "r"(dst), "l"(src));
}
__device__ __forceinline__ void ldsm4(uint32_t* f, uint32_t addr) {
    asm volatile("ldmatrix.sync.aligned.m8n8.x4.shared.b16 {%0,%1,%2,%3}, [%4];"
                 : "=r"(f[0]), "=r"(f[1]), "=r"(f[2]), "=r"(f[3]) : "r"(addr));
}
#define MMA_F16(acc, a, b0, b1)                                               \
    asm volatile(                                                             \
        "mma.sync.aligned.m16n8k16.row.col.f32.f16.f16.f32 "                  \
        "{%0,%1,%2,%3}, {%4,%5,%6,%7}, {%8,%9}, {%0,%1,%2,%3};"               \
        : "+f"((acc)[0]), "+f"((acc)[1]), "+f"((acc)[2]), "+f"((acc)[3])      \
        : "r"((a)[0]), "r"((a)[1]), "r"((a)[2]), "r"((a)[3]),                 \
          "r"(b0), "r"(b1))

__global__ __launch_bounds__(256) void mma_gemm_kernel(const float* __restrict__ b1)
{
    extern __shared__ char smem[];
    const uint32_t sbase = smem_u32(smem);
    const int tid  = threadIdx.x;
    const int lane = tid & 31;
    const int warp = tid >> 5;            // 0..7
    const int z  = blockIdx.z;
    const int m0 = blockIdx.y * 128;
    const int h0 = blockIdx.x * 128;
    float* __restrict__ C = z ? g_E : g_A;

    const int wm0 = (warp & 1) * 64;       // warp m offset: {0,64}
    const int wn0 = (warp >> 1) * 32;      // warp h offset: {0,32,64,96}
    const int lg  = lane >> 2;             // group id 0..7
    const int lq  = lane & 3;              // quad id 0..3

    // ldmatrix per-lane base offsets (within a tile)
    const int m4 = lane >> 3;
    const int r8 = lane & 7;
    const uint32_t aOff = (uint32_t)((wm0 + (m4 & 1) * 8 + r8) * ROW_B + (m4 >> 1) * 16);
    const uint32_t bOff = (uint32_t)((wn0 + (m4 >> 1) * 8 + r8) * ROW_B + (m4 & 1) * 16);

    float acc[4][4][4];
#pragma unroll
    for (int mi = 0; mi < 4; mi++)
#pragma unroll
        for (int ni = 0; ni < 4; ni++)
#pragma unroll
            for (int r = 0; r < 4; r++) acc[mi][ni][r] = 0.f;

    const int lrow = tid >> 4;             // 0..15
    const int lcol = tid & 15;             // int4 within 256B row

    const __half* Xh = g_Xh + (size_t)z * M_ROWS * VS;
    const __half* Wh = g_Wh + (size_t)z * VS * VS;

    auto issue = [&](int c) {
        const int k0 = c * 128;
        const uint32_t s0 = sbase + (c & 1) * STAGE;
#pragma unroll
        for (int i = 0; i < 8; i++) {
            const int row = i * 16 + lrow;
            const uint32_t d = (uint32_t)(row * ROW_B + lcol * 16);
            cp16(s0 + d,          Xh + (size_t)(m0 + row) * VS + k0 + lcol * 8);
            cp16(s0 + TILE_B + d, Wh + (size_t)(h0 + row) * VS + k0 + lcol * 8);
        }
        asm volatile("cp.async.commit_group;");
    };

    auto compute = [&](int c) {
        const uint32_t s0 = sbase + (c & 1) * STAGE;
        const uint32_t sA = s0 + aOff;
        const uint32_t sB = s0 + TILE_B + bOff;
#pragma unroll
        for (int kc = 0; kc < 8; kc++) {
            uint32_t bf[2][4];
            ldsm4(bf[0], sB + kc * 32);
            ldsm4(bf[1], sB + 16 * ROW_B + kc * 32);
#pragma unroll
            for (int mi = 0; mi < 4; mi++) {
                uint32_t a[4];
                ldsm4(a, sA + mi * 16 * ROW_B + kc * 32);
#pragma unroll
                for (int ni = 0; ni < 4; ni++)
                    MMA_F16(acc[mi][ni], a,
                            bf[ni >> 1][(ni & 1) * 2], bf[ni >> 1][(ni & 1) * 2 + 1]);
            }
        }
    };

    issue(0);
    for (int c = 0; c < NCHUNK; c++) {
        if (c + 1 < NCHUNK) {
            issue(c + 1);
            asm volatile("cp.async.wait_group 1;");
        } else {
            asm volatile("cp.async.wait_group 0;");
        }
        __syncthreads();
        compute(c);
        __syncthreads();
    }

    // Epilogue: bias (z==0) + float2 stores
#pragma unroll
    for (int mi = 0; mi < 4; mi++) {
        const int m = m0 + wm0 + mi * 16 + lg;
#pragma unroll
        for (int ni = 0; ni < 4; ni++) {
            const int h = h0 + wn0 + ni * 8 + lq * 2;
            float2 bias = make_float2(0.f, 0.f);
            if (z == 0) bias = *(const float2*)(b1 + h);
            float2 v0 = make_float2(acc[mi][ni][0] + bias.x, acc[mi][ni][1] + bias.y);
            float2 v1 = make_float2(acc[mi][ni][2] + bias.x, acc[mi][ni][3] + bias.y);
            *(float2*)(C + (size_t)m * VS + h)       = v0;
            *(float2*)(C + (size_t)(m + 8) * VS + h) = v1;
        }
    }
}

// ---------------------------------------------------------------------------
// Kernel 2: out[t,n,b] = sum_h w2[h]*tanh(A[t,b,h]+E[n,b,h]) + b2
// Block = (4 targets, b). 256 threads, E from L2, 16 MUFU chains per e-load.
// ---------------------------------------------------------------------------
#define TPB 4

__device__ __forceinline__ float tanh_fast(float x) {
    float y;
    asm("tanh.approx.f32 %0, %1;" : "=f"(y) : "f"(x));
    return y;
}

__global__ __launch_bounds__(256) void fuse_kernel(
    const float* __restrict__ W2, const float* __restrict__ b2,
    float* __restrict__ out)
{
    const int bb = blockIdx.y;
    const int t0 = blockIdx.x * TPB;
    const int warp = threadIdx.x >> 5;
    const int lane = threadIdx.x & 31;

    const float4* W4 = (const float4*)W2;
    float4 w[4];
#pragma unroll
    for (int j = 0; j < 4; j++) w[j] = __ldg(&W4[lane + 32 * j]);

    float4 a[TPB][4];
#pragma unroll
    for (int t = 0; t < TPB; t++) {
        const float4* A4 = (const float4*)(g_A + ((size_t)((t0 + t) * BATCH + bb)) * VS);
#pragma unroll
        for (int j = 0; j < 4; j++) a[t][j] = A4[lane + 32 * j];
    }
    const float b2v = __ldg(b2);

    for (int n = warp; n < NE; n += 8) {
        const float4* E4 = (const float4*)(g_E + ((size_t)(n * BATCH + bb)) * VS);
        float s[TPB] = {0.f, 0.f, 0.f, 0.f};
#pragma unroll
        for (int j = 0; j < 4; j++) {
            float4 e = __ldg(&E4[lane + 32 * j]);
#pragma unroll
            for (int t = 0; t < TPB; t++) {
                s[t] = fmaf(w[j].x, tanh_fast(a[t][j].x + e.x), s[t]);
                s[t] = fmaf(w[j].y, tanh_fast(a[t][j].y + e.y), s[t]);
                s[t] = fmaf(w[j].z, tanh_fast(a[t][j].z + e.z), s[t]);
                s[t] = fmaf(w[j].w, tanh_fast(a[t][j].w + e.w), s[t]);
            }
        }
#pragma unroll
        for (int off = 16; off; off >>= 1)
#pragma unroll
            for (int t = 0; t < TPB; t++)
                s[t] += __shfl_xor_sync(0xffffffffu, s[t], off);
        if (lane == 0) {
#pragma unroll
            for (int t = 0; t < TPB; t++)
                out[((size_t)(t0 + t) * NE + n) * BATCH + bb] = s[t] + b2v;
        }
    }
}

// ---------------------------------------------------------------------------
// Launch: inputs in metadata order: targets, embeddings, W1, b1, W2, b2
// ---------------------------------------------------------------------------
extern "C" void kernel_launch(void* const* d_in, const int* in_sizes, int n_in,
                              void* d_out, int out_size)
{
    const float* targets    = (const float*)d_in[0];
    const float* embeddings = (const float*)d_in[1];
    const float* W1         = (const float*)d_in[2];
    const float* b1         = (const float*)d_in[3];
    const float* W2         = (const float*)d_in[4];
    const float* b2         = (const float*)d_in[5];
    float* out = (float*)d_out;

    cudaFuncSetAttribute(mma_gemm_kernel,
                         cudaFuncAttributeMaxDynamicSharedMemorySize, GEMM_SMEM);

    const int nsplit = (NX4 + NW4 + 255) / 256;   // 2048 blocks
    split_kernel<<<nsplit, 256>>>(targets, embeddings, W1);

    dim3 gg(4, 12, 2);   // h-tiles, m-tiles, z
    mma_gemm_kernel<<<gg, 256, GEMM_SMEM>>>(b1);

    dim3 gf(NT / TPB, BATCH);   // 12 x 32
    fuse_kernel<<<gf, 256>>>(W2, b2, out);
}